// round 1
// baseline (speedup 1.0000x reference)
#include <cuda_runtime.h>
#include <math.h>

#define N_B   8
#define C_IN  64
#define C_OUT 128
#define KC    32
#define HH    256
#define WW    256
#define HW    65536
#define EPSI  1e-5f

// ---------------- scratch (device globals; no allocations allowed) ----------
__device__ float g_mixed[(size_t)N_B * C_IN * HW];            // 134 MB
__device__ float g_zpre [(size_t)N_B * C_OUT * HW];           // 268 MB
__device__ float g_kv   [(size_t)2 * N_B * KC * HW];          // 134 MB (K then V)
__device__ float g_stats[(size_t)N_B * C_OUT * 2];            // mean, inv_std
__device__ float g_ctx  [(size_t)N_B * KC];
__device__ float g_r    [(size_t)N_B * C_OUT];

#define KV_V_OFF ((size_t)N_B * KC * HW)

// ---------------- K1: mixed = (x - y) + x*y ---------------------------------
__global__ __launch_bounds__(256) void k_mix(const float* __restrict__ x,
                                             const float* __restrict__ y) {
    size_t i = ((size_t)blockIdx.x * 256 + threadIdx.x) * 4;
    float4 a = *(const float4*)(x + i);
    float4 b = *(const float4*)(y + i);
    float4 o;
    o.x = (a.x - b.x) + a.x * b.x;
    o.y = (a.y - b.y) + a.y * b.y;
    o.z = (a.z - b.z) + a.z * b.z;
    o.w = (a.w - b.w) + a.w * b.w;
    *(float4*)(g_mixed + i) = o;
}

// ---------------- K2: 3x3 conv 64->128 + bias + PReLU -----------------------
// Block: 256 threads. Tile: 32 output channels x (8 rows x 32 cols).
// Thread: 4 oc x 8 rows (one column). IC chunked by 16 through shared memory.
#define IC_CHUNK 16
__global__ __launch_bounds__(256) void k_conv(const float* __restrict__ cw,
                                              const float* __restrict__ cb,
                                              const float* __restrict__ pa_ptr) {
    __shared__ __align__(16) float s_in[IC_CHUNK][10][34];
    __shared__ __align__(16) float s_w[IC_CHUNK][9][32];   // [ic][tap][oc]

    const int tid = threadIdx.x;
    const int col = tid & 31;
    const int ocg = tid >> 5;                 // 0..7
    const int col0 = blockIdx.x * 32;         // 8 tiles
    const int row0 = blockIdx.y * 8;          // 32 tiles
    const int nz   = blockIdx.z;               // n*4 + oc_tile
    const int n    = nz >> 2;
    const int oc0  = (nz & 3) * 32;

    const float* inbase = g_mixed + (size_t)n * C_IN * HW;

    float acc[4][8];
#pragma unroll
    for (int a = 0; a < 4; a++)
#pragma unroll
        for (int r = 0; r < 8; r++) acc[a][r] = 0.f;

    for (int c0 = 0; c0 < C_IN; c0 += IC_CHUNK) {
        // load input tile (with zero padding at borders)
        for (int idx = tid; idx < IC_CHUNK * 10 * 34; idx += 256) {
            int ic  = idx / 340;
            int rem = idx - ic * 340;
            int yy  = rem / 34;
            int xx  = rem - yy * 34;
            int gy = row0 + yy - 1, gx = col0 + xx - 1;
            float v = 0.f;
            if (gy >= 0 && gy < HH && gx >= 0 && gx < WW)
                v = inbase[(size_t)(c0 + ic) * HW + (size_t)gy * WW + gx];
            s_in[ic][yy][xx] = v;
        }
        // load weights transposed: s_w[ic][tap][oc]
        for (int idx = tid; idx < IC_CHUNK * 9 * 32; idx += 256) {
            int ic  = idx / 288;
            int rem = idx - ic * 288;
            int tap = rem >> 5;
            int oc  = rem & 31;
            s_w[ic][tap][oc] = cw[(size_t)(oc0 + oc) * (C_IN * 9) + (c0 + ic) * 9 + tap];
        }
        __syncthreads();

        for (int ic = 0; ic < IC_CHUNK; ic++) {
#pragma unroll
            for (int dy = 0; dy < 3; dy++) {
#pragma unroll
                for (int dx = 0; dx < 3; dx++) {
                    float4 w4 = *(const float4*)&s_w[ic][dy * 3 + dx][ocg * 4];
                    float iv[8];
#pragma unroll
                    for (int r = 0; r < 8; r++) iv[r] = s_in[ic][r + dy][col + dx];
#pragma unroll
                    for (int r = 0; r < 8; r++) {
                        acc[0][r] += w4.x * iv[r];
                        acc[1][r] += w4.y * iv[r];
                        acc[2][r] += w4.z * iv[r];
                        acc[3][r] += w4.w * iv[r];
                    }
                }
            }
        }
        __syncthreads();
    }

    const float ap = *pa_ptr;
#pragma unroll
    for (int j = 0; j < 4; j++) {
        int oc = oc0 + ocg * 4 + j;
        float b = cb[oc];
        float* outp = g_zpre + (size_t)(n * C_OUT + oc) * HW + (size_t)row0 * WW + col0 + col;
#pragma unroll
        for (int r = 0; r < 8; r++) {
            float z = acc[j][r] + b;
            z = (z >= 0.f) ? z : ap * z;
            outp[(size_t)r * WW] = z;
        }
    }
}

// ---------------- K3: per-(n,c) mean / inv_std -------------------------------
__global__ __launch_bounds__(256) void k_stats() {
    const int nc = blockIdx.x;  // 0..1023
    const float4* p = (const float4*)(g_zpre + (size_t)nc * HW);
    float s = 0.f, ss = 0.f;
    for (int i = threadIdx.x; i < HW / 4; i += 256) {
        float4 v = p[i];
        s  += v.x + v.y + v.z + v.w;
        ss += v.x * v.x + v.y * v.y + v.z * v.z + v.w * v.w;
    }
    __shared__ float sm1[256], sm2[256];
    sm1[threadIdx.x] = s; sm2[threadIdx.x] = ss;
    __syncthreads();
    for (int st = 128; st > 0; st >>= 1) {
        if (threadIdx.x < st) {
            sm1[threadIdx.x] += sm1[threadIdx.x + st];
            sm2[threadIdx.x] += sm2[threadIdx.x + st];
        }
        __syncthreads();
    }
    if (threadIdx.x == 0) {
        float mean = sm1[0] * (1.f / HW);
        float var  = sm2[0] * (1.f / HW) - mean * mean;
        g_stats[nc * 2]     = mean;
        g_stats[nc * 2 + 1] = rsqrtf(var + EPSI);
    }
}

// ---------------- K4: fused normalize + K/V projection -----------------------
// K[n,h,s] = sum_c kw[h,c] * zn[n,c,s] + kb[h];  V likewise.
__global__ __launch_bounds__(256) void k_kv(const float* __restrict__ kw,
                                            const float* __restrict__ kb,
                                            const float* __restrict__ vw,
                                            const float* __restrict__ vb) {
    __shared__ __align__(16) float s_kw[C_OUT][KC];   // [c][h]
    __shared__ __align__(16) float s_vw[C_OUT][KC];
    __shared__ float s_mu[C_OUT], s_is[C_OUT];

    const int n = blockIdx.y;
    const int s = blockIdx.x * 256 + threadIdx.x;

    for (int idx = threadIdx.x; idx < C_OUT * KC; idx += 256) {
        int h = idx & (KC - 1);
        int c = idx >> 5;
        s_kw[c][h] = kw[h * C_OUT + c];
        s_vw[c][h] = vw[h * C_OUT + c];
    }
    for (int idx = threadIdx.x; idx < C_OUT; idx += 256) {
        s_mu[idx] = g_stats[(n * C_OUT + idx) * 2];
        s_is[idx] = g_stats[(n * C_OUT + idx) * 2 + 1];
    }
    __syncthreads();

    float ka[KC], va[KC];
#pragma unroll
    for (int h = 0; h < KC; h++) { ka[h] = 0.f; va[h] = 0.f; }

    const float* zp = g_zpre + (size_t)n * C_OUT * HW + s;
#pragma unroll 4
    for (int c = 0; c < C_OUT; c++) {
        float zc = (zp[(size_t)c * HW] - s_mu[c]) * s_is[c];
#pragma unroll
        for (int h4 = 0; h4 < KC / 4; h4++) {
            float4 w = *(const float4*)&s_kw[c][h4 * 4];
            ka[h4 * 4 + 0] += w.x * zc;
            ka[h4 * 4 + 1] += w.y * zc;
            ka[h4 * 4 + 2] += w.z * zc;
            ka[h4 * 4 + 3] += w.w * zc;
            float4 v = *(const float4*)&s_vw[c][h4 * 4];
            va[h4 * 4 + 0] += v.x * zc;
            va[h4 * 4 + 1] += v.y * zc;
            va[h4 * 4 + 2] += v.z * zc;
            va[h4 * 4 + 3] += v.w * zc;
        }
    }
#pragma unroll
    for (int h = 0; h < KC; h++) {
        g_kv[(size_t)(n * KC + h) * HW + s]            = ka[h] + kb[h];
        g_kv[KV_V_OFF + (size_t)(n * KC + h) * HW + s] = va[h] + vb[h];
    }
}

// ---------------- K5: ctx[n,h] = softmax_s(K[n,h,:]) . V[n,h,:] --------------
__global__ __launch_bounds__(256) void k_ctx() {
    const int nh = blockIdx.x;  // 0..255
    const float* K = g_kv + (size_t)nh * HW;
    const float* V = g_kv + KV_V_OFF + (size_t)nh * HW;
    const int tid = threadIdx.x;

    float m = -1e30f, s1 = 0.f, s2 = 0.f;
    for (int i = tid; i < HW; i += 256) {
        float k = K[i], v = V[i];
        float nm = fmaxf(m, k);
        float eo = __expf(m - nm);
        float e  = __expf(k - nm);
        s1 = s1 * eo + e;
        s2 = s2 * eo + e * v;
        m = nm;
    }
    __shared__ float sm[256], ss1[256], ss2[256];
    sm[tid] = m; ss1[tid] = s1; ss2[tid] = s2;
    __syncthreads();
    for (int st = 128; st > 0; st >>= 1) {
        if (tid < st) {
            float m2 = sm[tid + st], a = ss1[tid + st], b = ss2[tid + st];
            float nm = fmaxf(sm[tid], m2);
            float e1 = __expf(sm[tid] - nm), e2 = __expf(m2 - nm);
            ss1[tid] = ss1[tid] * e1 + a * e2;
            ss2[tid] = ss2[tid] * e1 + b * e2;
            sm[tid] = nm;
        }
        __syncthreads();
    }
    if (tid == 0) g_ctx[nh] = ss2[0] / ss1[0];
}

// ---------------- K6: r[n,c] = reproj_w[c,:] . ctx[n,:] + rb[c] --------------
__global__ void k_reproj(const float* __restrict__ rw, const float* __restrict__ rb) {
    int i = blockIdx.x * 256 + threadIdx.x;
    if (i >= N_B * C_OUT) return;
    int n = i >> 7, c = i & 127;
    float acc = rb[c];
#pragma unroll
    for (int v = 0; v < KC; v++) acc += rw[c * KC + v] * g_ctx[n * KC + v];
    g_r[i] = acc;
}

// ---------------- K7: out = (zpre - mu)*inv_std + r --------------------------
__global__ __launch_bounds__(256) void k_out(float* __restrict__ out) {
    const int nc = blockIdx.y;  // 0..1023
    const float mu = g_stats[nc * 2];
    const float is = g_stats[nc * 2 + 1];
    const float r  = g_r[nc];
    const size_t base = (size_t)nc * HW;
    const size_t i = ((size_t)blockIdx.x * 256 + threadIdx.x) * 4;
    float4 z = *(const float4*)(g_zpre + base + i);
    float4 o;
    o.x = (z.x - mu) * is + r;
    o.y = (z.y - mu) * is + r;
    o.z = (z.z - mu) * is + r;
    o.w = (z.w - mu) * is + r;
    *(float4*)(out + base + i) = o;
}

// ---------------- launcher ---------------------------------------------------
extern "C" void kernel_launch(void* const* d_in, const int* in_sizes, int n_in,
                              void* d_out, int out_size) {
    const float* x   = (const float*)d_in[0];
    const float* y   = (const float*)d_in[1];
    const float* cw  = (const float*)d_in[2];
    const float* cb  = (const float*)d_in[3];
    const float* pa  = (const float*)d_in[4];
    const float* kw  = (const float*)d_in[5];
    const float* kb  = (const float*)d_in[6];
    // d_in[7], d_in[8] = queries (mathematically unused: softmax over size-1 axis == 1)
    const float* vw  = (const float*)d_in[9];
    const float* vb  = (const float*)d_in[10];
    const float* rw  = (const float*)d_in[11];
    const float* rb  = (const float*)d_in[12];
    float* out = (float*)d_out;

    // K1: mixed
    {
        size_t total = (size_t)N_B * C_IN * HW;
        k_mix<<<(unsigned)(total / 1024), 256>>>(x, y);
    }
    // K2: conv + PReLU
    {
        dim3 grid(WW / 32, HH / 8, N_B * (C_OUT / 32));
        k_conv<<<grid, 256>>>(cw, cb, pa);
    }
    // K3: instance-norm stats
    k_stats<<<N_B * C_OUT, 256>>>();
    // K4: K/V projections on normalized z
    {
        dim3 grid(HW / 256, N_B);
        k_kv<<<grid, 256>>>(kw, kb, vw, vb);
    }
    // K5: per-(n,head) softmax context
    k_ctx<<<N_B * KC, 256>>>();
    // K6: reprojection scalars
    k_reproj<<<(N_B * C_OUT + 255) / 256, 256>>>(rw, rb);
    // K7: epilogue
    {
        dim3 grid(HW / 1024, N_B * C_OUT);
        k_out<<<grid, 256>>>(out);
    }
}